// round 16
// baseline (speedup 1.0000x reference)
#include <cuda_runtime.h>

// Shapes: B=32, N=128, IN_CH=16, IN_DIM=32, OUT_CH=32, OUT_DIM=32, P=2048
// x[b,n,c,i]  : b*65536 + n*512 + c*32 + i
// W[c,o,i,j]  : c*32768 + o*1024 + i*32 + j
// y/z[b,o,c,i]: (b*32+o)*512 + c*32 + i
// b_ij is linear in the z-history: b_t = x . (z_0+..+z_{t-1}); never materialized.
// k_f: fused du+y pass with packed fma.rn.f32x2 (k_f is FMA-issue-bound).
// k_s: scalar, W-loaded-once (latency-bound; best measured variant, unchanged).

typedef unsigned long long u64;

__device__ __forceinline__ u64 pk(float a, float b) {
    u64 r; asm("mov.b64 %0,{%1,%2};" : "=l"(r) : "f"(a), "f"(b)); return r;
}
__device__ __forceinline__ void upk(u64 p, float& a, float& b) {
    asm("mov.b64 {%0,%1},%2;" : "=f"(a), "=f"(b) : "l"(p));
}
__device__ __forceinline__ void fma2(u64& d, u64 a, u64 b) {
    asm("fma.rn.f32x2 %0,%1,%2,%0;" : "+l"(d) : "l"(a), "l"(b));
}

__device__ __align__(16) float g_y  [32*32*16*32];
__device__ __align__(16) float g_y0p[32*8*512];
__device__ __align__(16) float g_z  [32*32*16*32];
__device__ float g_sp [32*16*32];
__device__ float g_mp [32*16*32];
__device__ float g_t  [32*32];

// ---------------------------------------------------------------------------
__global__ void k_y0(const float* __restrict__ x)
{
    int b = blockIdx.x >> 3, k = blockIdx.x & 7, t = threadIdx.x;
    const float* xb = x + b*65536 + k*16*512 + t;
    float acc = 0.f;
    #pragma unroll
    for (int n = 0; n < 16; ++n) acc += xb[n*512];
    g_y0p[b*4096 + k*512 + t] = acc * (1.f/2048.f);
}

// ---------------------------------------------------------------------------
// k_f: fused routing step. grid 128, 512 threads, 4 (b,c) tiles per block.
// Per tile: du[n,o] = x[n,:].z[o,:], w = exp(du-toff), y[o,i] += w*x[n,i],
// all in ONE pass; du and y both via packed FFMA2.
// ---------------------------------------------------------------------------
#define SMEM_KF (23168*4)
__global__ __launch_bounds__(512) void k_f(const float* __restrict__ x,
                                           int use_toff, int write_mp)
{
    extern __shared__ __align__(16) float sm[];
    float* x_sm    = sm;            // [128][32]
    float* z_sm    = sm + 4096;     // [32][34]  (even stride: u64 pair loads)
    float* mred    = sm + 5184;     // [16][33]
    float* sred    = sm + 5712;     // [16][33]
    float* toff_sm = sm + 6240;     // [32]
    u64*   yred    = (u64*)(sm + 6272);  // [(wid*16+q)*33 + lane]

    const int t = threadIdx.x, lane = t & 31, wid = t >> 5;

    for (int q4 = 0; q4 < 4; ++q4) {
        int tile = blockIdx.x*4 + q4;
        int b = tile >> 4, c = tile & 15;

        const float* xb = x + b*65536 + c*32;
        #pragma unroll
        for (int nn = 0; nn < 8; ++nn) {
            int n = wid*8 + nn;
            x_sm[n*32 + lane] = xb[n*512 + lane];
        }
        {   // z slice, stride-34 rows
            int oo = t >> 4, i2 = t & 15;
            const float* zg = g_z + (b*32 + oo)*512 + c*32;
            *(float2*)(z_sm + oo*34 + 2*i2) = make_float2(zg[2*i2], zg[2*i2+1]);
        }
        if (t < 32) toff_sm[t] = use_toff ? g_t[b*32 + t] : 0.f;
        __syncthreads();

        // z row for o = lane as 16 packed pairs (once per tile)
        u64 zr2[16];
        #pragma unroll
        for (int q = 0; q < 16; ++q) zr2[q] = *(const u64*)(z_sm + lane*34 + 2*q);

        float toff = toff_sm[lane];
        float bmax = -1e30f, ssum = 0.f;
        u64 yacc2[16];
        #pragma unroll
        for (int q = 0; q < 16; ++q) yacc2[q] = 0;

        #pragma unroll
        for (int nn = 0; nn < 8; ++nn) {
            int n = wid*8 + nn;
            const ulonglong2* xr = (const ulonglong2*)(x_sm + n*32);  // bcast
            ulonglong2 xq[8];
            u64 a0 = 0, a1 = 0;
            #pragma unroll
            for (int k = 0; k < 8; ++k) {          // du dot (packed)
                xq[k] = xr[k];
                fma2(a0, xq[k].x, zr2[2*k]);
                fma2(a1, xq[k].y, zr2[2*k+1]);
            }
            float l0,h0,l1,h1; upk(a0,l0,h0); upk(a1,l1,h1);
            float du = (l0+h0)+(l1+h1);
            bmax = fmaxf(bmax, du);
            float w = __expf(du - toff);
            ssum += w;
            u64 ws = pk(w, w);
            #pragma unroll
            for (int k = 0; k < 8; ++k) {          // y[o,i] += w*x[n,i] (packed)
                fma2(yacc2[2*k],   xq[k].x, ws);
                fma2(yacc2[2*k+1], xq[k].y, ws);
            }
        }
        mred[wid*33 + lane] = bmax;
        sred[wid*33 + lane] = ssum;
        #pragma unroll
        for (int q = 0; q < 16; ++q)
            yred[(wid*16 + q)*33 + lane] = yacc2[q];
        __syncthreads();

        if (t < 32) {
            float m = -1e30f, s = 0.f;
            #pragma unroll
            for (int g = 0; g < 16; ++g) {
                m = fmaxf(m, mred[g*33 + t]);
                s += sred[g*33 + t];
            }
            if (write_mp) g_mp[b*512 + c*32 + t] = m;
            g_sp[b*512 + c*32 + t] = s;
        }
        {   // y reduction: thread (o = t>>4, q = t&15) sums 16 warp partials
            int o = t >> 4, q = t & 15;
            float a = 0.f, bv = 0.f;
            #pragma unroll
            for (int w = 0; w < 16; ++w) {
                float ua, ub; upk(yred[(w*16 + q)*33 + o], ua, ub);
                a += ua; bv += ub;
            }
            float2* yp = (float2*)(g_y + (b*32 + o)*512 + c*32) + q;
            *yp = make_float2(a, bv);
        }
        __syncthreads();
    }
}

// ---------------------------------------------------------------------------
// k_s: s[b,o,j] = (1/S) sum_ci y[b,o,ci] W[ci,o,j]; squash -> v,a;
//      z_cum[b,o,ci] (+)= sum_j W[ci,o,j] v[b,o,j]
// grid 128 (o | b-group of 8), 512 threads. W loaded once (coalesced),
// consumed once by s-loop (reused over 8 b) and once by z-loop. All scalar.
// ---------------------------------------------------------------------------
#define SMEM_KS (27040*4)
__global__ __launch_bounds__(512) void k_s(const float* __restrict__ Wg,
                                           int mode, float* __restrict__ out)
{
    extern __shared__ __align__(16) float sm[];
    float* W36  = sm;              // [512][36]
    float* y_sm = sm + 18432;      // [8][512]
    float* part = sm + 22528;      // [16][8][33]
    float* v_sm = sm + 26752;      // [8][36]

    int o  = blockIdx.x & 31;
    int b0 = (blockIdx.x >> 5) * 8;
    int t  = threadIdx.x;

    // W o-slice, coalesced -> [ci][36]
    const float4* W4 = (const float4*)Wg;
    #pragma unroll
    for (int k = 0; k < 8; ++k) {
        int gi = k*512 + t;
        int c = gi >> 8, tt = gi & 255;
        float4 w = W4[c*8192 + o*256 + tt];
        int i = tt >> 3, j0 = (tt & 7) * 4;
        *(float4*)(W36 + (c*32 + i)*36 + j0) = w;
    }
    // y for 8 b's
    #pragma unroll
    for (int q = 0; q < 2; ++q) {
        int idx = q*512 + t, bb = idx >> 7, ci4 = idx & 127;
        float4 val;
        if (mode == 0) {
            const float4* yp = (const float4*)g_y0p + (b0+bb)*1024 + ci4;
            val = yp[0];
            #pragma unroll
            for (int k = 1; k < 8; ++k) {
                float4 v = yp[k*128];
                val.x += v.x; val.y += v.y; val.z += v.z; val.w += v.w;
            }
        } else {
            val = ((const float4*)(g_y + (b0+bb)*16384 + o*512))[ci4];
        }
        *(float4*)(y_sm + bb*512 + ci4*4) = val;
    }
    __syncthreads();

    int j = t & 31, w5 = t >> 5;
    int ci_base = w5 * 32;

    // s-loop: warp owns 32-ci strip for all 8 b; scalar W (CF), bcast y
    float acc[8];
    #pragma unroll
    for (int b = 0; b < 8; ++b) acc[b] = 0.f;
    #pragma unroll 2
    for (int g = 0; g < 8; ++g) {
        int ci0 = ci_base + g*4;
        const float* wp = W36 + ci0*36 + j;
        float w0 = wp[0], w1 = wp[36], w2 = wp[72], w3 = wp[108];
        #pragma unroll
        for (int b = 0; b < 8; ++b) {
            float4 yv = *(const float4*)(y_sm + b*512 + ci0);   // broadcast
            acc[b] = fmaf(yv.w, w3, fmaf(yv.z, w2,
                     fmaf(yv.y, w1, fmaf(yv.x, w0, acc[b]))));
        }
    }
    #pragma unroll
    for (int b = 0; b < 8; ++b) part[w5*264 + b*33 + j] = acc[b];
    __syncthreads();

    if (w5 < 8) {                  // warp = b
        int b = b0 + w5;
        float sacc = 0.f;
        #pragma unroll
        for (int e = 0; e < 16; ++e) sacc += part[e*264 + w5*33 + j];
        float Sinv = 1.f;
        if (mode != 0) {
            float sv = (j < 16) ? g_sp[b*512 + j*32 + o] : 0.f;
            #pragma unroll
            for (int s2 = 16; s2; s2 >>= 1) sv += __shfl_xor_sync(0xffffffffu, sv, s2);
            Sinv = 1.f / sv;
            if (mode == 1) {
                float mv = (j < 16) ? g_mp[b*512 + j*32 + o] : -1e30f;
                #pragma unroll
                for (int s2 = 16; s2; s2 >>= 1)
                    mv = fmaxf(mv, __shfl_xor_sync(0xffffffffu, mv, s2));
                if (j == 0) g_t[b*32 + o] = mv;
            }
        }
        float accv = sacc * Sinv;
        float mag_sq = accv*accv;
        #pragma unroll
        for (int s2 = 16; s2; s2 >>= 1) mag_sq += __shfl_xor_sync(0xffffffffu, mag_sq, s2);
        float mag = sqrtf(mag_sq) + 1e-11f;
        float a   = mag_sq / (1.f + mag_sq);
        float v   = accv * (a / mag);
        v_sm[w5*36 + j] = v;
        if (mode == 2) {
            out[(b*32 + o)*32 + j] = v;
            if (j == 0) out[32768 + b*32 + o] = a;
        }
    }
    if (mode == 2) return;
    __syncthreads();

    // z-loop: lane = (lb = j&7 -> b, lc = j>>3 -> ci offset); W rows bcast
    {
        int lb = j & 7, lc = j >> 3;
        float vp[32];
        const float4* vv = (const float4*)(v_sm + lb*36);      // bcast per lb
        #pragma unroll
        for (int k = 0; k < 8; ++k) {
            float4 u = vv[k];
            vp[4*k] = u.x; vp[4*k+1] = u.y; vp[4*k+2] = u.z; vp[4*k+3] = u.w;
        }
        float* zrow = g_z + ((b0 + lb)*32 + o)*512;
        #pragma unroll
        for (int it = 0; it < 8; ++it) {
            int ci = ci_base + it*4 + lc;
            const float4* wr = (const float4*)(W36 + ci*36);   // bcast x8
            float z = 0.f;
            #pragma unroll
            for (int k = 0; k < 8; ++k) {
                float4 wq = wr[k];
                z = fmaf(wq.x, vp[4*k], z);
                z = fmaf(wq.y, vp[4*k+1], z);
                z = fmaf(wq.z, vp[4*k+2], z);
                z = fmaf(wq.w, vp[4*k+3], z);
            }
            if (mode == 1) z += zrow[ci];
            zrow[ci] = z;
        }
    }
}

// ---------------------------------------------------------------------------
extern "C" void kernel_launch(void* const* d_in, const int* in_sizes, int n_in,
                              void* d_out, int out_size)
{
    const float* x = (const float*)d_in[0];
    const float* W = (const float*)(n_in > 1 ? d_in[1] : d_in[0]);
    for (int i = 0; i < n_in; ++i) {
        if (in_sizes[i] == 32*128*16*32)      x = (const float*)d_in[i];
        else if (in_sizes[i] == 16*32*32*32)  W = (const float*)d_in[i];
    }
    float* out = (float*)d_out;

    cudaFuncSetAttribute(k_s, cudaFuncAttributeMaxDynamicSharedMemorySize, SMEM_KS);
    cudaFuncSetAttribute(k_f, cudaFuncAttributeMaxDynamicSharedMemorySize, SMEM_KF);

    k_y0<<<256, 512>>>(x);
    k_s <<<128, 512, SMEM_KS>>>(W, 0, nullptr);   // v0, z_cum = z0
    k_f <<<128, 512, SMEM_KF>>>(x, 0, 1);         // y1, S + max partials
    k_s <<<128, 512, SMEM_KS>>>(W, 1, nullptr);   // v1, z_cum += z1, g_t
    k_f <<<128, 512, SMEM_KF>>>(x, 1, 0);         // y2, S
    k_s <<<128, 512, SMEM_KS>>>(W, 2, out);       // v2, a2 -> out
}

// round 17
// speedup vs baseline: 1.4926x; 1.4926x over previous
#include <cuda_runtime.h>

// Shapes: B=32, N=128, IN_CH=16, IN_DIM=32, OUT_CH=32, OUT_DIM=32, P=2048
// x[b,n,c,i]  : b*65536 + n*512 + c*32 + i
// W[c,o,i,j]  : c*32768 + o*1024 + i*32 + j
// y/z[b,o,c,i]: (b*32+o)*512 + c*32 + i
// b_ij is linear in the z-history: b_t = x . (z_0+..+z_{t-1}); never materialized.
// All-scalar fp32 (packed-f32x2 variants measured neutral-to-regressive).
// k_f fuses the du GEMM and the y GEMM (x float4s held in registers).
// k_s z-loop uses 4 independent accumulator chains (RAW-latency fix).

typedef unsigned long long u64;

__device__ __forceinline__ u64 pk(float a, float b) {
    u64 r; asm("mov.b64 %0,{%1,%2};" : "=l"(r) : "f"(a), "f"(b)); return r;
}
__device__ __forceinline__ void upk(u64 p, float& a, float& b) {
    asm("mov.b64 {%0,%1},%2;" : "=f"(a), "=f"(b) : "l"(p));
}

__device__ __align__(16) float g_y  [32*32*16*32];
__device__ __align__(16) float g_y0p[32*8*512];
__device__ __align__(16) float g_z  [32*32*16*32];
__device__ float g_sp [32*16*32];
__device__ float g_mp [32*16*32];
__device__ float g_t  [32*32];

// ---------------------------------------------------------------------------
__global__ void k_y0(const float* __restrict__ x)
{
    int b = blockIdx.x >> 3, k = blockIdx.x & 7, t = threadIdx.x;
    const float* xb = x + b*65536 + k*16*512 + t;
    float a0 = 0.f, a1 = 0.f;
    #pragma unroll
    for (int n = 0; n < 16; n += 2) {
        a0 += xb[n*512];
        a1 += xb[(n+1)*512];
    }
    g_y0p[b*4096 + k*512 + t] = (a0 + a1) * (1.f/2048.f);
}

// ---------------------------------------------------------------------------
// k_f: fused routing step. grid 128, 512 threads, 4 (b,c) tiles per block.
// Per tile: du[n,o] = x[n,:].z[o,:], w = exp(du-toff), and y[o,i] += w*x[n,i]
// computed in ONE pass (x float4s held in registers between the two uses).
// ---------------------------------------------------------------------------
#define SMEM_KF (23136*4)
__global__ __launch_bounds__(512) void k_f(const float* __restrict__ x,
                                           int use_toff, int write_mp)
{
    extern __shared__ __align__(16) float sm[];
    float* x_sm    = sm;            // [128][32]
    float* z_sm    = sm + 4096;     // [32][33]  (stride 33: CF scalar reads)
    float* mred    = sm + 5152;     // [16][33]
    float* sred    = sm + 5680;     // [16][33]
    float* toff_sm = sm + 6208;     // [32]
    u64*   yred    = (u64*)(sm + 6240);  // [(wid*16+q)*33 + lane]

    const int t = threadIdx.x, lane = t & 31, wid = t >> 5;

    for (int q4 = 0; q4 < 4; ++q4) {
        int tile = blockIdx.x*4 + q4;
        int b = tile >> 4, c = tile & 15;

        const float* xb = x + b*65536 + c*32;
        #pragma unroll
        for (int nn = 0; nn < 8; ++nn) {
            int n = wid*8 + nn;
            x_sm[n*32 + lane] = xb[n*512 + lane];
        }
        {   // z slice, scalar (stride-33 rows)
            int oo = t >> 4, i2 = t & 15;
            const float* zg = g_z + (b*32 + oo)*512 + c*32;
            z_sm[oo*33 + i2]      = zg[i2];
            z_sm[oo*33 + i2 + 16] = zg[i2 + 16];
        }
        if (t < 32) toff_sm[t] = use_toff ? g_t[b*32 + t] : 0.f;
        __syncthreads();

        // z row for o = lane (CF scalar LDS, once per tile)
        float zr[32];
        #pragma unroll
        for (int i = 0; i < 32; ++i) zr[i] = z_sm[lane*33 + i];

        float toff = toff_sm[lane];
        float bmax = -1e30f, ssum = 0.f;
        float yacc[32];
        #pragma unroll
        for (int i = 0; i < 32; ++i) yacc[i] = 0.f;

        #pragma unroll
        for (int nn = 0; nn < 8; ++nn) {
            int n = wid*8 + nn;
            const float4* xr = (const float4*)(x_sm + n*32);  // broadcast
            float4 xq[8];
            float d0 = 0.f, d1 = 0.f, d2 = 0.f, d3 = 0.f;
            #pragma unroll
            for (int k = 0; k < 8; ++k) {
                xq[k] = xr[k];
                d0 = fmaf(xq[k].x, zr[4*k+0], d0);
                d1 = fmaf(xq[k].y, zr[4*k+1], d1);
                d2 = fmaf(xq[k].z, zr[4*k+2], d2);
                d3 = fmaf(xq[k].w, zr[4*k+3], d3);
            }
            float du = (d0+d1)+(d2+d3);
            bmax = fmaxf(bmax, du);
            float w = __expf(du - toff);
            ssum += w;
            #pragma unroll
            for (int k = 0; k < 8; ++k) {       // y[o,i] += w * x[n,i]
                yacc[4*k+0] = fmaf(w, xq[k].x, yacc[4*k+0]);
                yacc[4*k+1] = fmaf(w, xq[k].y, yacc[4*k+1]);
                yacc[4*k+2] = fmaf(w, xq[k].z, yacc[4*k+2]);
                yacc[4*k+3] = fmaf(w, xq[k].w, yacc[4*k+3]);
            }
        }
        mred[wid*33 + lane] = bmax;
        sred[wid*33 + lane] = ssum;
        #pragma unroll
        for (int q = 0; q < 16; ++q)
            yred[(wid*16 + q)*33 + lane] = pk(yacc[2*q], yacc[2*q+1]);
        __syncthreads();

        if (t < 32) {
            float m = -1e30f, s = 0.f;
            #pragma unroll
            for (int g = 0; g < 16; ++g) {
                m = fmaxf(m, mred[g*33 + t]);
                s += sred[g*33 + t];
            }
            if (write_mp) g_mp[b*512 + c*32 + t] = m;
            g_sp[b*512 + c*32 + t] = s;
        }
        {   // y reduction: thread (o = t>>4, q = t&15) sums 16 warp partials
            int o = t >> 4, q = t & 15;
            float a = 0.f, bv = 0.f;
            #pragma unroll
            for (int w = 0; w < 16; ++w) {
                float ua, ub; upk(yred[(w*16 + q)*33 + o], ua, ub);
                a += ua; bv += ub;
            }
            float2* yp = (float2*)(g_y + (b*32 + o)*512 + c*32) + q;
            *yp = make_float2(a, bv);
        }
        __syncthreads();
    }
}

// ---------------------------------------------------------------------------
// k_s: s[b,o,j] = (1/S) sum_ci y[b,o,ci] W[ci,o,j]; squash -> v,a;
//      z_cum[b,o,ci] (+)= sum_j W[ci,o,j] v[b,o,j]
// grid 128 (o | b-group of 8), 512 threads. W loaded once (coalesced),
// consumed once by s-loop (reused over 8 b) and once by z-loop. All scalar.
// z-loop: 4 independent FFMA chains (was 1 chain of depth 32).
// ---------------------------------------------------------------------------
#define SMEM_KS (27040*4)
__global__ __launch_bounds__(512) void k_s(const float* __restrict__ Wg,
                                           int mode, float* __restrict__ out)
{
    extern __shared__ __align__(16) float sm[];
    float* W36  = sm;              // [512][36]
    float* y_sm = sm + 18432;      // [8][512]
    float* part = sm + 22528;      // [16][8][33]
    float* v_sm = sm + 26752;      // [8][36]

    int o  = blockIdx.x & 31;
    int b0 = (blockIdx.x >> 5) * 8;
    int t  = threadIdx.x;

    // W o-slice, coalesced -> [ci][36]
    const float4* W4 = (const float4*)Wg;
    #pragma unroll
    for (int k = 0; k < 8; ++k) {
        int gi = k*512 + t;
        int c = gi >> 8, tt = gi & 255;
        float4 w = W4[c*8192 + o*256 + tt];
        int i = tt >> 3, j0 = (tt & 7) * 4;
        *(float4*)(W36 + (c*32 + i)*36 + j0) = w;
    }
    // y for 8 b's
    #pragma unroll
    for (int q = 0; q < 2; ++q) {
        int idx = q*512 + t, bb = idx >> 7, ci4 = idx & 127;
        float4 val;
        if (mode == 0) {
            const float4* yp = (const float4*)g_y0p + (b0+bb)*1024 + ci4;
            float4 e = yp[0], f = yp[128];
            #pragma unroll
            for (int k = 2; k < 8; k += 2) {
                float4 u = yp[k*128], v = yp[(k+1)*128];
                e.x += u.x; e.y += u.y; e.z += u.z; e.w += u.w;
                f.x += v.x; f.y += v.y; f.z += v.z; f.w += v.w;
            }
            val = make_float4(e.x+f.x, e.y+f.y, e.z+f.z, e.w+f.w);
        } else {
            val = ((const float4*)(g_y + (b0+bb)*16384 + o*512))[ci4];
        }
        *(float4*)(y_sm + bb*512 + ci4*4) = val;
    }
    __syncthreads();

    int j = t & 31, w5 = t >> 5;
    int ci_base = w5 * 32;

    // s-loop: warp owns 32-ci strip for all 8 b; scalar W (CF), bcast y
    float acc[8];
    #pragma unroll
    for (int b = 0; b < 8; ++b) acc[b] = 0.f;
    #pragma unroll 2
    for (int g = 0; g < 8; ++g) {
        int ci0 = ci_base + g*4;
        const float* wp = W36 + ci0*36 + j;
        float w0 = wp[0], w1 = wp[36], w2 = wp[72], w3 = wp[108];
        #pragma unroll
        for (int b = 0; b < 8; ++b) {
            float4 yv = *(const float4*)(y_sm + b*512 + ci0);   // broadcast
            acc[b] = fmaf(yv.w, w3, fmaf(yv.z, w2,
                     fmaf(yv.y, w1, fmaf(yv.x, w0, acc[b]))));
        }
    }
    #pragma unroll
    for (int b = 0; b < 8; ++b) part[w5*264 + b*33 + j] = acc[b];
    __syncthreads();

    if (w5 < 8) {                  // warp = b
        int b = b0 + w5;
        float s0 = 0.f, s1 = 0.f;
        #pragma unroll
        for (int e = 0; e < 16; e += 2) {
            s0 += part[e*264 + w5*33 + j];
            s1 += part[(e+1)*264 + w5*33 + j];
        }
        float sacc = s0 + s1;
        float Sinv = 1.f;
        if (mode != 0) {
            float sv = (j < 16) ? g_sp[b*512 + j*32 + o] : 0.f;
            #pragma unroll
            for (int s2 = 16; s2; s2 >>= 1) sv += __shfl_xor_sync(0xffffffffu, sv, s2);
            Sinv = 1.f / sv;
            if (mode == 1) {
                float mv = (j < 16) ? g_mp[b*512 + j*32 + o] : -1e30f;
                #pragma unroll
                for (int s2 = 16; s2; s2 >>= 1)
                    mv = fmaxf(mv, __shfl_xor_sync(0xffffffffu, mv, s2));
                if (j == 0) g_t[b*32 + o] = mv;
            }
        }
        float accv = sacc * Sinv;
        float mag_sq = accv*accv;
        #pragma unroll
        for (int s2 = 16; s2; s2 >>= 1) mag_sq += __shfl_xor_sync(0xffffffffu, mag_sq, s2);
        float mag = sqrtf(mag_sq) + 1e-11f;
        float a   = mag_sq / (1.f + mag_sq);
        float v   = accv * (a / mag);
        v_sm[w5*36 + j] = v;
        if (mode == 2) {
            out[(b*32 + o)*32 + j] = v;
            if (j == 0) out[32768 + b*32 + o] = a;
        }
    }
    if (mode == 2) return;
    __syncthreads();

    // z-loop: lane = (lb = j&7 -> b, lc = j>>3 -> ci offset); W rows bcast.
    // 4 independent accumulator chains per output (RAW depth 8, not 32).
    {
        int lb = j & 7, lc = j >> 3;
        float vp[32];
        const float4* vv = (const float4*)(v_sm + lb*36);      // bcast per lb
        #pragma unroll
        for (int k = 0; k < 8; ++k) {
            float4 u = vv[k];
            vp[4*k] = u.x; vp[4*k+1] = u.y; vp[4*k+2] = u.z; vp[4*k+3] = u.w;
        }
        float* zrow = g_z + ((b0 + lb)*32 + o)*512;
        #pragma unroll
        for (int it = 0; it < 8; ++it) {
            int ci = ci_base + it*4 + lc;
            const float4* wr = (const float4*)(W36 + ci*36);   // bcast x8
            float z0 = 0.f, z1 = 0.f, z2 = 0.f, z3 = 0.f;
            #pragma unroll
            for (int k = 0; k < 8; ++k) {
                float4 wq = wr[k];
                z0 = fmaf(wq.x, vp[4*k],   z0);
                z1 = fmaf(wq.y, vp[4*k+1], z1);
                z2 = fmaf(wq.z, vp[4*k+2], z2);
                z3 = fmaf(wq.w, vp[4*k+3], z3);
            }
            float z = (z0 + z1) + (z2 + z3);
            if (mode == 1) z += zrow[ci];
            zrow[ci] = z;
        }
    }
}

// ---------------------------------------------------------------------------
extern "C" void kernel_launch(void* const* d_in, const int* in_sizes, int n_in,
                              void* d_out, int out_size)
{
    const float* x = (const float*)d_in[0];
    const float* W = (const float*)(n_in > 1 ? d_in[1] : d_in[0]);
    for (int i = 0; i < n_in; ++i) {
        if (in_sizes[i] == 32*128*16*32)      x = (const float*)d_in[i];
        else if (in_sizes[i] == 16*32*32*32)  W = (const float*)d_in[i];
    }
    float* out = (float*)d_out;

    cudaFuncSetAttribute(k_s, cudaFuncAttributeMaxDynamicSharedMemorySize, SMEM_KS);
    cudaFuncSetAttribute(k_f, cudaFuncAttributeMaxDynamicSharedMemorySize, SMEM_KF);

    k_y0<<<256, 512>>>(x);
    k_s <<<128, 512, SMEM_KS>>>(W, 0, nullptr);   // v0, z_cum = z0
    k_f <<<128, 512, SMEM_KF>>>(x, 0, 1);         // y1, S + max partials
    k_s <<<128, 512, SMEM_KS>>>(W, 1, nullptr);   // v1, z_cum += z1, g_t
    k_f <<<128, 512, SMEM_KF>>>(x, 1, 0);         // y2, S
    k_s <<<128, 512, SMEM_KS>>>(W, 2, out);       // v2, a2 -> out
}